// round 8
// baseline (speedup 1.0000x reference)
#include <cuda_runtime.h>
#include <cuda_fp16.h>
#include <cstdint>

// LightGCN propagation, pull formulation, fp16 storage / fp32 accumulate.
// CSR build (hist + shfl-scan + fill), pulls with 16 threads/node:
// 8 feature-lanes x 2 edge-parity groups, uint4 fp16 gathers, f32x2 FMA.
//   h1 = fp16(A h0) ; h2 = fp16(A h1)
//   out = 0.25 * (x0_fp32 + h1 + h2 + A h2)

#define N_USERS   100000
#define N_ITEMS   50000
#define N_TOTAL   150000
#define EMB_DIM   64
#define N_EDGES   2000000
#define N_ELEMS   (N_TOTAL * EMB_DIM)
#define N_F4      (N_ELEMS / 4)            // uint2 units (prep)
#define N_U4      (N_ELEMS / 8)            // uint4 units per buffer

#define SCAN_BLK  1024
#define N_SCANBLK ((N_TOTAL + SCAN_BLK - 1) / SCAN_BLK)   // 147

// fp16 feature buffers: 64 halves = 8 uint4 per row (19.2 MB each)
__device__ uint4 g_h0[N_U4];
__device__ uint4 g_h1[N_U4];
__device__ uint4 g_h2[N_U4];

// CSR scratch
__device__ int   g_deg[N_TOTAL];
__device__ int   g_off[N_TOTAL + 1];
__device__ int   g_cursor[N_TOTAL];
__device__ int   g_partials[N_SCANBLK];
__device__ int   g_blockoff[N_SCANBLK];
__device__ int2  g_cw[N_EDGES];            // {col, weight-bits}, row-sorted

__device__ int   g_idx_is64;

// ---------------------------------------------------------------------------
__device__ __forceinline__ uint2 pack_h4(float4 v) {
    __half2 a = __float22half2_rn(make_float2(v.x, v.y));
    __half2 b = __float22half2_rn(make_float2(v.z, v.w));
    uint2 r;
    r.x = *(unsigned int*)&a;
    r.y = *(unsigned int*)&b;
    return r;
}

// ---------------------------------------------------------------------------
// prep: zero degree hist + convert x0 -> fp16 + dtype detect (block 0)
// ---------------------------------------------------------------------------
__global__ void prep_kernel(const long long* __restrict__ ei64,
                            const float4* __restrict__ user,
                            const float4* __restrict__ item) {
    int i = blockIdx.x * blockDim.x + threadIdx.x;
    if (i < N_TOTAL) g_deg[i] = 0;
    if (i < N_F4) {
        const int USER_F4 = (N_USERS * EMB_DIM) / 4;
        float4 v = (i < USER_F4) ? __ldg(&user[i]) : __ldg(&item[i - USER_F4]);
        ((uint2*)g_h0)[i] = pack_h4(v);
    }
    if (blockIdx.x == 0) {
        __shared__ int ok;
        if (threadIdx.x == 0) ok = 1;
        __syncthreads();
        long long v = ei64[threadIdx.x];
        if (v < 0 || v >= N_TOTAL) atomicAnd(&ok, 0);
        __syncthreads();
        if (threadIdx.x == 0) g_idx_is64 = ok;
    }
}

// ---------------------------------------------------------------------------
__global__ void hist_kernel(const void* __restrict__ edge_index) {
    int e = blockIdx.x * blockDim.x + threadIdx.x;
    if (e >= N_EDGES) return;
    int r;
    if (__ldg(&g_idx_is64)) r = (int)__ldg(&((const long long*)edge_index)[e]);
    else                    r = __ldg(&((const int*)edge_index)[e]);
    atomicAdd(&g_deg[r], 1);
}

// ---------------------------------------------------------------------------
// scan1: per-block inclusive scan via warp shuffles -> g_off[i+1], partials
// ---------------------------------------------------------------------------
__global__ void scan1_kernel() {
    __shared__ int warpsum[32];
    int i = blockIdx.x * SCAN_BLK + threadIdx.x;
    int lane = threadIdx.x & 31;
    int wid  = threadIdx.x >> 5;
    int v = (i < N_TOTAL) ? g_deg[i] : 0;

    int x = v;
#pragma unroll
    for (int d = 1; d < 32; d <<= 1) {
        int y = __shfl_up_sync(0xffffffffu, x, d);
        if (lane >= d) x += y;
    }
    if (lane == 31) warpsum[wid] = x;
    __syncthreads();
    if (wid == 0) {
        int s = warpsum[lane];
#pragma unroll
        for (int d = 1; d < 32; d <<= 1) {
            int y = __shfl_up_sync(0xffffffffu, s, d);
            if (lane >= d) s += y;
        }
        warpsum[lane] = s;
    }
    __syncthreads();
    int incl = x + ((wid > 0) ? warpsum[wid - 1] : 0);
    if (i < N_TOTAL) g_off[i + 1] = incl;             // block-local inclusive
    if (threadIdx.x == SCAN_BLK - 1) g_partials[blockIdx.x] = incl;
}

// ---------------------------------------------------------------------------
// scan2: exclusive scan of 147 partials in one warp (5 elems/lane)
// ---------------------------------------------------------------------------
__global__ void scan2_kernel() {
    const int CHUNK = (N_SCANBLK + 31) / 32;          // 5
    int lane = threadIdx.x;                           // 32 threads
    int pref[CHUNK];
    int s = 0;
#pragma unroll
    for (int k = 0; k < CHUNK; k++) {
        int idx = lane * CHUNK + k;
        int v = (idx < N_SCANBLK) ? g_partials[idx] : 0;
        pref[k] = s;                                  // exclusive within chunk
        s += v;
    }
    int x = s;
#pragma unroll
    for (int d = 1; d < 32; d <<= 1) {
        int y = __shfl_up_sync(0xffffffffu, x, d);
        if (lane >= d) x += y;
    }
    int excl = x - s;
#pragma unroll
    for (int k = 0; k < CHUNK; k++) {
        int idx = lane * CHUNK + k;
        if (idx < N_SCANBLK) g_blockoff[idx] = excl + pref[k];
    }
}

// ---------------------------------------------------------------------------
// scan3: add block offsets in place, derive fill cursors
// ---------------------------------------------------------------------------
__global__ void scan3_kernel() {
    int i = blockIdx.x * blockDim.x + threadIdx.x;
    if (i >= N_TOTAL) return;
    int incl = g_off[i + 1] + g_blockoff[i >> 10];
    g_off[i + 1] = incl;
    g_cursor[i]  = incl - g_deg[i];
    if (i == 0) g_off[0] = 0;
}

// ---------------------------------------------------------------------------
__global__ void fill_kernel(const void* __restrict__ edge_index,
                            const float* __restrict__ edge_weight) {
    int e = blockIdx.x * blockDim.x + threadIdx.x;
    if (e >= N_EDGES) return;
    int r, c;
    if (__ldg(&g_idx_is64)) {
        const long long* ei = (const long long*)edge_index;
        r = (int)__ldg(&ei[e]);
        c = (int)__ldg(&ei[N_EDGES + e]);
    } else {
        const int* ei = (const int*)edge_index;
        r = __ldg(&ei[e]);
        c = __ldg(&ei[N_EDGES + e]);
    }
    int p = atomicAdd(&g_cursor[r], 1);
    g_cw[p] = make_int2(c, __float_as_int(__ldg(&edge_weight[e])));
}

// ---------------------------------------------------------------------------
// pull: 16 threads/node = 8 feature-lanes (uint4 each) x 2 edge-parity groups.
// fp16 gather -> fp32 accumulate with packed fma.rn.f32x2.
// Parity partials combined via 64-bit shfl_xor + add.rn.f32x2.
// ---------------------------------------------------------------------------
template <int FINAL>
__global__ void pull_kernel(const uint4* __restrict__ src,
                            uint4* __restrict__ dst,
                            const float4* __restrict__ eu,
                            const float4* __restrict__ ei,
                            const uint4* __restrict__ h1,
                            const uint4* __restrict__ h2,
                            float4* __restrict__ out) {
    int gid = blockIdx.x * blockDim.x + threadIdx.x;
    int n   = gid >> 4;
    int sub = (gid >> 3) & 1;
    int j   = gid & 7;
    if (n >= N_TOTAL) return;

    int s = __ldg(&g_off[n]);
    int t = __ldg(&g_off[n + 1]);

    unsigned long long acc0 = 0ull, acc1 = 0ull, acc2 = 0ull, acc3 = 0ull;
    const uint4* lanebase = src + j;

#define EDGE_STEP(EE)                                                         \
    {                                                                         \
        int2 cw = __ldg(&g_cw[EE]);                                           \
        float wf = __int_as_float(cw.y);                                      \
        unsigned long long wpk;                                               \
        asm("mov.b64 %0, {%1, %1};" : "=l"(wpk) : "f"(wf));                   \
        uint4 p = __ldg(lanebase + (size_t)cw.x * 8);                         \
        float2 f0 = __half22float2(*(__half2*)&p.x);                          \
        float2 f1 = __half22float2(*(__half2*)&p.y);                          \
        float2 f2 = __half22float2(*(__half2*)&p.z);                          \
        float2 f3 = __half22float2(*(__half2*)&p.w);                          \
        unsigned long long v0, v1, v2, v3;                                    \
        asm("mov.b64 %0, {%1, %2};" : "=l"(v0) : "f"(f0.x), "f"(f0.y));       \
        asm("mov.b64 %0, {%1, %2};" : "=l"(v1) : "f"(f1.x), "f"(f1.y));       \
        asm("mov.b64 %0, {%1, %2};" : "=l"(v2) : "f"(f2.x), "f"(f2.y));       \
        asm("mov.b64 %0, {%1, %2};" : "=l"(v3) : "f"(f3.x), "f"(f3.y));       \
        asm("fma.rn.f32x2 %0, %1, %2, %0;" : "+l"(acc0) : "l"(v0), "l"(wpk)); \
        asm("fma.rn.f32x2 %0, %1, %2, %0;" : "+l"(acc1) : "l"(v1), "l"(wpk)); \
        asm("fma.rn.f32x2 %0, %1, %2, %0;" : "+l"(acc2) : "l"(v2), "l"(wpk)); \
        asm("fma.rn.f32x2 %0, %1, %2, %0;" : "+l"(acc3) : "l"(v3), "l"(wpk)); \
    }

    int e = s + sub;
    for (; e + 6 < t; e += 8) {
        EDGE_STEP(e) EDGE_STEP(e + 2) EDGE_STEP(e + 4) EDGE_STEP(e + 6)
    }
    for (; e < t; e += 2) {
        EDGE_STEP(e)
    }
#undef EDGE_STEP

    // combine parity partials (lanes j and j+8 of each 16-lane group)
    {
        unsigned long long o;
        o = __shfl_xor_sync(0xffffffffu, acc0, 8);
        asm("add.rn.f32x2 %0, %0, %1;" : "+l"(acc0) : "l"(o));
        o = __shfl_xor_sync(0xffffffffu, acc1, 8);
        asm("add.rn.f32x2 %0, %0, %1;" : "+l"(acc1) : "l"(o));
        o = __shfl_xor_sync(0xffffffffu, acc2, 8);
        asm("add.rn.f32x2 %0, %0, %1;" : "+l"(acc2) : "l"(o));
        o = __shfl_xor_sync(0xffffffffu, acc3, 8);
        asm("add.rn.f32x2 %0, %0, %1;" : "+l"(acc3) : "l"(o));
    }
    if (sub != 0) return;

    float a0, a1, a2, a3, a4, a5, a6, a7;
    asm("mov.b64 {%0, %1}, %2;" : "=f"(a0), "=f"(a1) : "l"(acc0));
    asm("mov.b64 {%0, %1}, %2;" : "=f"(a2), "=f"(a3) : "l"(acc1));
    asm("mov.b64 {%0, %1}, %2;" : "=f"(a4), "=f"(a5) : "l"(acc2));
    asm("mov.b64 {%0, %1}, %2;" : "=f"(a6), "=f"(a7) : "l"(acc3));

    long long oi = (long long)n * 8 + j;
    if (FINAL) {
        long long fi = (long long)n * 16 + 2 * j;
        float4 x0a, x0b;
        if (n < N_USERS) {
            x0a = __ldg(&eu[fi]);
            x0b = __ldg(&eu[fi + 1]);
        } else {
            long long ii = (long long)(n - N_USERS) * 16 + 2 * j;
            x0a = __ldg(&ei[ii]);
            x0b = __ldg(&ei[ii + 1]);
        }
        uint4 p1 = __ldg(&h1[oi]);
        uint4 p2 = __ldg(&h2[oi]);
        float2 u0 = __half22float2(*(__half2*)&p1.x);
        float2 u1 = __half22float2(*(__half2*)&p1.y);
        float2 u2 = __half22float2(*(__half2*)&p1.z);
        float2 u3 = __half22float2(*(__half2*)&p1.w);
        float2 v0 = __half22float2(*(__half2*)&p2.x);
        float2 v1 = __half22float2(*(__half2*)&p2.y);
        float2 v2 = __half22float2(*(__half2*)&p2.z);
        float2 v3 = __half22float2(*(__half2*)&p2.w);
        out[fi]     = make_float4((x0a.x + u0.x + v0.x + a0) * 0.25f,
                                  (x0a.y + u0.y + v0.y + a1) * 0.25f,
                                  (x0a.z + u1.x + v1.x + a2) * 0.25f,
                                  (x0a.w + u1.y + v1.y + a3) * 0.25f);
        out[fi + 1] = make_float4((x0b.x + u2.x + v2.x + a4) * 0.25f,
                                  (x0b.y + u2.y + v2.y + a5) * 0.25f,
                                  (x0b.z + u3.x + v3.x + a6) * 0.25f,
                                  (x0b.w + u3.y + v3.y + a7) * 0.25f);
    } else {
        uint2 lo = pack_h4(make_float4(a0, a1, a2, a3));
        uint2 hi = pack_h4(make_float4(a4, a5, a6, a7));
        dst[oi] = make_uint4(lo.x, lo.y, hi.x, hi.y);
    }
}

extern "C" void kernel_launch(void* const* d_in, const int* in_sizes, int n_in,
                              void* d_out, int out_size) {
    const void* edge_index   = d_in[0];
    const float* edge_weight = (const float*)d_in[1];
    const float4* user_emb   = (const float4*)d_in[2];
    const float4* item_emb   = (const float4*)d_in[3];
    float4* out              = (float4*)d_out;

    uint4 *h0, *h1, *h2;
    cudaGetSymbolAddress((void**)&h0, g_h0);
    cudaGetSymbolAddress((void**)&h1, g_h1);
    cudaGetSymbolAddress((void**)&h2, g_h2);

    const int TPB = 256;
    const int GRID_PREP = (N_F4 + TPB - 1) / TPB;
    const int GRID_EDGE = (N_EDGES + TPB - 1) / TPB;
    const int GRID_NODE = (N_TOTAL + TPB - 1) / TPB;
    const int GRID_PULL = (N_TOTAL * 16 + TPB - 1) / TPB;

    prep_kernel<<<GRID_PREP, TPB>>>((const long long*)edge_index,
                                    user_emb, item_emb);

    // CSR build
    hist_kernel<<<GRID_EDGE, TPB>>>(edge_index);
    scan1_kernel<<<N_SCANBLK, SCAN_BLK>>>();
    scan2_kernel<<<1, 32>>>();
    scan3_kernel<<<GRID_NODE, TPB>>>();
    fill_kernel<<<GRID_EDGE, TPB>>>(edge_index, edge_weight);

    // h1 = A h0 ; h2 = A h1 ; out = 0.25*(x0 + h1 + h2 + A h2)
    pull_kernel<0><<<GRID_PULL, TPB>>>(h0, h1, nullptr, nullptr,
                                       nullptr, nullptr, nullptr);
    pull_kernel<0><<<GRID_PULL, TPB>>>(h1, h2, nullptr, nullptr,
                                       nullptr, nullptr, nullptr);
    pull_kernel<1><<<GRID_PULL, TPB>>>(h2, nullptr, user_emb, item_emb,
                                       h1, h2, out);
}

// round 9
// speedup vs baseline: 1.2101x; 1.2101x over previous
#include <cuda_runtime.h>
#include <cuda_fp16.h>
#include <cstdint>

// LightGCN propagation, pull formulation, fp16 storage / fp32 accumulate.
// CSR build (hist + shfl scans + fill); pulls: 16 threads/node, uint2 fp16
// gathers (R5 shape, empirical best), __launch_bounds__ for full occupancy.
//   h1 = fp16(A h0) ; h2 = fp16(A h1)
//   out = 0.25 * (x0_fp32 + h1 + h2 + A h2)

#define N_USERS   100000
#define N_ITEMS   50000
#define N_TOTAL   150000
#define EMB_DIM   64
#define N_EDGES   2000000
#define N_ELEMS   (N_TOTAL * EMB_DIM)
#define N_F4      (N_ELEMS / 4)            // 2,400,000 uint2 units

#define SCAN_BLK  1024
#define N_SCANBLK ((N_TOTAL + SCAN_BLK - 1) / SCAN_BLK)   // 147

// fp16 feature buffers: 64 halves = 16 uint2 per row (19.2 MB each)
__device__ uint2 g_h0[N_F4];
__device__ uint2 g_h1[N_F4];
__device__ uint2 g_h2[N_F4];

// CSR scratch
__device__ int   g_deg[N_TOTAL];
__device__ int   g_off[N_TOTAL + 1];
__device__ int   g_cursor[N_TOTAL];
__device__ int   g_partials[N_SCANBLK];
__device__ int   g_blockoff[N_SCANBLK];
__device__ int2  g_cw[N_EDGES];            // {col, weight-bits}, row-sorted

__device__ int   g_idx_is64;

// ---------------------------------------------------------------------------
__device__ __forceinline__ uint2 pack_h4(float4 v) {
    __half2 a = __float22half2_rn(make_float2(v.x, v.y));
    __half2 b = __float22half2_rn(make_float2(v.z, v.w));
    uint2 r;
    r.x = *(unsigned int*)&a;
    r.y = *(unsigned int*)&b;
    return r;
}

// ---------------------------------------------------------------------------
// prep: zero degree hist + convert x0 -> fp16 + dtype detect (block 0)
// ---------------------------------------------------------------------------
__global__ void prep_kernel(const long long* __restrict__ ei64,
                            const float4* __restrict__ user,
                            const float4* __restrict__ item) {
    int i = blockIdx.x * blockDim.x + threadIdx.x;
    if (i < N_TOTAL) g_deg[i] = 0;
    if (i < N_F4) {
        const int USER_F4 = (N_USERS * EMB_DIM) / 4;
        float4 v = (i < USER_F4) ? __ldg(&user[i]) : __ldg(&item[i - USER_F4]);
        g_h0[i] = pack_h4(v);
    }
    if (blockIdx.x == 0) {
        __shared__ int ok;
        if (threadIdx.x == 0) ok = 1;
        __syncthreads();
        long long v = ei64[threadIdx.x];
        if (v < 0 || v >= N_TOTAL) atomicAnd(&ok, 0);
        __syncthreads();
        if (threadIdx.x == 0) g_idx_is64 = ok;
    }
}

// ---------------------------------------------------------------------------
__global__ void hist_kernel(const void* __restrict__ edge_index) {
    int e = blockIdx.x * blockDim.x + threadIdx.x;
    if (e >= N_EDGES) return;
    int r;
    if (__ldg(&g_idx_is64)) r = (int)__ldg(&((const long long*)edge_index)[e]);
    else                    r = __ldg(&((const int*)edge_index)[e]);
    atomicAdd(&g_deg[r], 1);
}

// ---------------------------------------------------------------------------
// scan1: per-block inclusive scan via warp shuffles -> g_off[i+1], partials
// ---------------------------------------------------------------------------
__global__ void scan1_kernel() {
    __shared__ int warpsum[32];
    int i = blockIdx.x * SCAN_BLK + threadIdx.x;
    int lane = threadIdx.x & 31;
    int wid  = threadIdx.x >> 5;
    int v = (i < N_TOTAL) ? g_deg[i] : 0;

    int x = v;
#pragma unroll
    for (int d = 1; d < 32; d <<= 1) {
        int y = __shfl_up_sync(0xffffffffu, x, d);
        if (lane >= d) x += y;
    }
    if (lane == 31) warpsum[wid] = x;
    __syncthreads();
    if (wid == 0) {
        int s = warpsum[lane];
#pragma unroll
        for (int d = 1; d < 32; d <<= 1) {
            int y = __shfl_up_sync(0xffffffffu, s, d);
            if (lane >= d) s += y;
        }
        warpsum[lane] = s;
    }
    __syncthreads();
    int incl = x + ((wid > 0) ? warpsum[wid - 1] : 0);
    if (i < N_TOTAL) g_off[i + 1] = incl;             // block-local inclusive
    if (threadIdx.x == SCAN_BLK - 1) g_partials[blockIdx.x] = incl;
}

// ---------------------------------------------------------------------------
// scan2: exclusive scan of 147 partials in one warp (5 elems/lane)
// ---------------------------------------------------------------------------
__global__ void scan2_kernel() {
    const int CHUNK = (N_SCANBLK + 31) / 32;          // 5
    int lane = threadIdx.x;                           // 32 threads
    int pref[CHUNK];
    int s = 0;
#pragma unroll
    for (int k = 0; k < CHUNK; k++) {
        int idx = lane * CHUNK + k;
        int v = (idx < N_SCANBLK) ? g_partials[idx] : 0;
        pref[k] = s;
        s += v;
    }
    int x = s;
#pragma unroll
    for (int d = 1; d < 32; d <<= 1) {
        int y = __shfl_up_sync(0xffffffffu, x, d);
        if (lane >= d) x += y;
    }
    int excl = x - s;
#pragma unroll
    for (int k = 0; k < CHUNK; k++) {
        int idx = lane * CHUNK + k;
        if (idx < N_SCANBLK) g_blockoff[idx] = excl + pref[k];
    }
}

// ---------------------------------------------------------------------------
__global__ void scan3_kernel() {
    int i = blockIdx.x * blockDim.x + threadIdx.x;
    if (i >= N_TOTAL) return;
    int incl = g_off[i + 1] + g_blockoff[i >> 10];
    g_off[i + 1] = incl;
    g_cursor[i]  = incl - g_deg[i];
    if (i == 0) g_off[0] = 0;
}

// ---------------------------------------------------------------------------
__global__ void fill_kernel(const void* __restrict__ edge_index,
                            const float* __restrict__ edge_weight) {
    int e = blockIdx.x * blockDim.x + threadIdx.x;
    if (e >= N_EDGES) return;
    int r, c;
    if (__ldg(&g_idx_is64)) {
        const long long* ei = (const long long*)edge_index;
        r = (int)__ldg(&ei[e]);
        c = (int)__ldg(&ei[N_EDGES + e]);
    } else {
        const int* ei = (const int*)edge_index;
        r = __ldg(&ei[e]);
        c = __ldg(&ei[N_EDGES + e]);
    }
    int p = atomicAdd(&g_cursor[r], 1);
    g_cw[p] = make_int2(c, __float_as_int(__ldg(&edge_weight[e])));
}

// ---------------------------------------------------------------------------
// pull: 16 threads per node, lane j owns 4 features (one uint2 of half2s).
// Gather fp16, accumulate fp32. __launch_bounds__ forces regs<=32 so 8 blocks
// (64 warps) fit per SM — full occupancy for latency hiding.
// FINAL=0: write fp16 row to dst.
// FINAL=1: out = 0.25 * (x0_fp32 + h1 + h2 + a), fp32 output.
// ---------------------------------------------------------------------------
template <int FINAL>
__global__ void __launch_bounds__(256, 8)
pull_kernel(const uint2* __restrict__ src,
            uint2* __restrict__ dst,
            const float4* __restrict__ eu,   // x0 user (fp32)
            const float4* __restrict__ ei,   // x0 item (fp32)
            const uint2* __restrict__ h1,
            const uint2* __restrict__ h2,
            float4* __restrict__ out) {
    int gid = blockIdx.x * blockDim.x + threadIdx.x;
    int n = gid >> 4;
    int j = gid & 15;
    if (n >= N_TOTAL) return;

    int s = __ldg(&g_off[n]);
    int t = __ldg(&g_off[n + 1]);

    float ax = 0.f, ay = 0.f, az = 0.f, aw = 0.f;
    int e = s;

#define EDGE_STEP(K)                                                          \
    {                                                                         \
        int2 cw = __ldg(&g_cw[e + K]);                                        \
        float w = __int_as_float(cw.y);                                       \
        uint2 p = __ldg(&src[(long long)cw.x * 16 + j]);                      \
        float2 f01 = __half22float2(*(__half2*)&p.x);                         \
        float2 f23 = __half22float2(*(__half2*)&p.y);                         \
        ax += f01.x * w; ay += f01.y * w;                                     \
        az += f23.x * w; aw += f23.y * w;                                     \
    }

    for (; e + 4 <= t; e += 4) {
        EDGE_STEP(0) EDGE_STEP(1) EDGE_STEP(2) EDGE_STEP(3)
    }
    for (; e < t; e++) {
        EDGE_STEP(0)
    }
#undef EDGE_STEP

    long long oi = (long long)n * 16 + j;
    if (FINAL) {
        float4 x0 = (n < N_USERS)
                        ? __ldg(&eu[oi])
                        : __ldg(&ei[(long long)(n - N_USERS) * 16 + j]);
        uint2 p1 = __ldg(&h1[oi]);
        uint2 p2 = __ldg(&h2[oi]);
        float2 a01 = __half22float2(*(__half2*)&p1.x);
        float2 a23 = __half22float2(*(__half2*)&p1.y);
        float2 b01 = __half22float2(*(__half2*)&p2.x);
        float2 b23 = __half22float2(*(__half2*)&p2.y);
        out[oi] = make_float4((x0.x + a01.x + b01.x + ax) * 0.25f,
                              (x0.y + a01.y + b01.y + ay) * 0.25f,
                              (x0.z + a23.x + b23.x + az) * 0.25f,
                              (x0.w + a23.y + b23.y + aw) * 0.25f);
    } else {
        dst[oi] = pack_h4(make_float4(ax, ay, az, aw));
    }
}

extern "C" void kernel_launch(void* const* d_in, const int* in_sizes, int n_in,
                              void* d_out, int out_size) {
    const void* edge_index   = d_in[0];
    const float* edge_weight = (const float*)d_in[1];
    const float4* user_emb   = (const float4*)d_in[2];
    const float4* item_emb   = (const float4*)d_in[3];
    float4* out              = (float4*)d_out;

    uint2 *h0, *h1, *h2;
    cudaGetSymbolAddress((void**)&h0, g_h0);
    cudaGetSymbolAddress((void**)&h1, g_h1);
    cudaGetSymbolAddress((void**)&h2, g_h2);

    const int TPB = 256;
    const int GRID_PREP = (N_F4 + TPB - 1) / TPB;
    const int GRID_EDGE = (N_EDGES + TPB - 1) / TPB;
    const int GRID_NODE = (N_TOTAL + TPB - 1) / TPB;
    const int GRID_PULL = (N_TOTAL * 16 + TPB - 1) / TPB;

    prep_kernel<<<GRID_PREP, TPB>>>((const long long*)edge_index,
                                    user_emb, item_emb);

    // CSR build
    hist_kernel<<<GRID_EDGE, TPB>>>(edge_index);
    scan1_kernel<<<N_SCANBLK, SCAN_BLK>>>();
    scan2_kernel<<<1, 32>>>();
    scan3_kernel<<<GRID_NODE, TPB>>>();
    fill_kernel<<<GRID_EDGE, TPB>>>(edge_index, edge_weight);

    // h1 = A h0 ; h2 = A h1 ; out = 0.25*(x0 + h1 + h2 + A h2)
    pull_kernel<0><<<GRID_PULL, TPB>>>(h0, h1, nullptr, nullptr,
                                       nullptr, nullptr, nullptr);
    pull_kernel<0><<<GRID_PULL, TPB>>>(h1, h2, nullptr, nullptr,
                                       nullptr, nullptr, nullptr);
    pull_kernel<1><<<GRID_PULL, TPB>>>(h2, nullptr, user_emb, item_emb,
                                       h1, h2, out);
}